// round 4
// baseline (speedup 1.0000x reference)
#include <cuda_runtime.h>
#include <cstdint>

// Problem constants (fixed by the reference).
#define ROWS       8192
#define COLS       8192
#define NUMEL      (1ULL * ROWS * COLS)          // 64M output floats
#define NCODES     (NUMEL / 4)                   // 16M codes (centroid_len = 4)
#define CB_ENTRIES 512                           // 2 codebooks * 256 centroids (float4 each)

#define BLOCK      256
#define BLOCKS_PER_SM 8
#define CODES_PER_THREAD 8
#define TILE_CODES (BLOCK * CODES_PER_THREAD)    // 2048
#define NTILES     ((int)(NCODES / TILE_CODES))  // 8192 (exact)
#define GRID       (152 * BLOCKS_PER_SM)         // 1216

// Codebook staged to smem once per block. Each block owns a CONTIGUOUS,
// balanced range of tiles (sequential DRAM sweep, good row locality).
// Interleaved per-thread layout inside a tile keeps every LDG/STG coalesced.
// Streaming cache hints: codes/output are touched exactly once.
__global__ __launch_bounds__(BLOCK, BLOCKS_PER_SM) void dequant_kernel(
    const float4* __restrict__ codebooks,   // [512] float4
    const float*  __restrict__ scales,      // [NUMEL/64]
    const int*    __restrict__ codes,       // [NCODES]
    float4*       __restrict__ out4)        // [NCODES]
{
    __shared__ float4 s_cb[CB_ENTRIES];
    for (int i = threadIdx.x; i < CB_ENTRIES; i += BLOCK)
        s_cb[i] = codebooks[i];
    __syncthreads();

    const int t = threadIdx.x;

    // Balanced contiguous partition: first `rem` blocks get (base+1) tiles.
    const int base_cnt = NTILES / GRID;              // 6
    const int rem      = NTILES % GRID;              // 896
    const int cnt   = base_cnt + (blockIdx.x < rem ? 1 : 0);
    const int first = blockIdx.x * base_cnt + min((int)blockIdx.x, rem);

    for (int tile = first; tile < first + cnt; tile++) {
        const long long base = (long long)tile * TILE_CODES;
        // Codebook half: first 8M codes -> cb 0, rest -> cb 1.
        // 8M / 2048 = 4096 tiles fall entirely in the first half.
        const int cb_off = (tile >= (NTILES / 2)) ? 256 : 0;

        const int*   cp = codes  + base;
        const float* sp = scales + (base >> 4);   // one scale per 16 codes
        float4*      op = out4   + base;

        int   c[CODES_PER_THREAD];
        float s[CODES_PER_THREAD];

        // Front-batch all global loads (MLP ~16, each instruction coalesced).
        #pragma unroll
        for (int k = 0; k < CODES_PER_THREAD; k++)
            c[k] = __ldcs(cp + k * BLOCK + t);          // streaming: no reuse
        #pragma unroll
        for (int k = 0; k < CODES_PER_THREAD; k++)
            s[k] = __ldg(sp + ((k * BLOCK + t) >> 4));  // shared within block -> cache

        // Gather from smem codebook, scale, store (coalesced STG.128, streaming).
        #pragma unroll
        for (int k = 0; k < CODES_PER_THREAD; k++) {
            float4 v = s_cb[cb_off + c[k]];
            v.x *= s[k]; v.y *= s[k]; v.z *= s[k]; v.w *= s[k];
            __stcs(op + k * BLOCK + t, v);
        }
    }
}

extern "C" void kernel_launch(void* const* d_in, const int* in_sizes, int n_in,
                              void* d_out, int out_size)
{
    // metadata order: codebooks [2,256,4] f32, scales [1M,1] f32, codes [2,8M] i32, rows, columns
    const float4* codebooks = (const float4*)d_in[0];
    const float*  scales    = (const float*)d_in[1];
    const int*    codes     = (const int*)d_in[2];
    float4*       out4      = (float4*)d_out;

    dequant_kernel<<<GRID, BLOCK>>>(codebooks, scales, codes, out4);
}

// round 5
// speedup vs baseline: 1.0110x; 1.0110x over previous
#include <cuda_runtime.h>
#include <cstdint>

// Problem constants (fixed by the reference).
#define ROWS       8192
#define COLS       8192
#define NUMEL      (1ULL * ROWS * COLS)          // 64M output floats
#define NCODES     (NUMEL / 4)                   // 16M codes (centroid_len = 4)
#define CB_ENTRIES 512                           // 2 codebooks * 256 centroids (float4 each)

#define BLOCK      256
#define BLOCKS_PER_SM 8
#define CODES_PER_THREAD 8
#define TILE_CODES (BLOCK * CODES_PER_THREAD)    // 2048
#define NTILES     ((int)(NCODES / TILE_CODES))  // 8192 (exact)
#define GRID       (152 * BLOCKS_PER_SM)         // 1216

// Codebook staged to smem once per block. Each block owns a CONTIGUOUS,
// balanced range of tiles (sequential DRAM sweep, good row locality).
// Interleaved per-thread layout inside a tile keeps every LDG/STG coalesced.
// Streaming cache hints: codes/output are touched exactly once.
__global__ __launch_bounds__(BLOCK, BLOCKS_PER_SM) void dequant_kernel(
    const float4* __restrict__ codebooks,   // [512] float4
    const float*  __restrict__ scales,      // [NUMEL/64]
    const int*    __restrict__ codes,       // [NCODES]
    float4*       __restrict__ out4)        // [NCODES]
{
    __shared__ float4 s_cb[CB_ENTRIES];
    for (int i = threadIdx.x; i < CB_ENTRIES; i += BLOCK)
        s_cb[i] = codebooks[i];
    __syncthreads();

    const int t = threadIdx.x;

    // Balanced contiguous partition: first `rem` blocks get (base+1) tiles.
    const int base_cnt = NTILES / GRID;              // 6
    const int rem      = NTILES % GRID;              // 896
    const int cnt   = base_cnt + (blockIdx.x < rem ? 1 : 0);
    const int first = blockIdx.x * base_cnt + min((int)blockIdx.x, rem);

    for (int tile = first; tile < first + cnt; tile++) {
        const long long base = (long long)tile * TILE_CODES;
        // Codebook half: first 8M codes -> cb 0, rest -> cb 1.
        // 8M / 2048 = 4096 tiles fall entirely in the first half.
        const int cb_off = (tile >= (NTILES / 2)) ? 256 : 0;

        const int*   cp = codes  + base;
        const float* sp = scales + (base >> 4);   // one scale per 16 codes
        float4*      op = out4   + base;

        int   c[CODES_PER_THREAD];
        float s[CODES_PER_THREAD];

        // Front-batch all global loads (MLP ~16, each instruction coalesced).
        #pragma unroll
        for (int k = 0; k < CODES_PER_THREAD; k++)
            c[k] = __ldcs(cp + k * BLOCK + t);          // streaming: no reuse
        #pragma unroll
        for (int k = 0; k < CODES_PER_THREAD; k++)
            s[k] = __ldg(sp + ((k * BLOCK + t) >> 4));  // shared within block -> cache

        // Gather from smem codebook, scale, store (coalesced STG.128, streaming).
        #pragma unroll
        for (int k = 0; k < CODES_PER_THREAD; k++) {
            float4 v = s_cb[cb_off + c[k]];
            v.x *= s[k]; v.y *= s[k]; v.z *= s[k]; v.w *= s[k];
            __stcs(op + k * BLOCK + t, v);
        }
    }
}

extern "C" void kernel_launch(void* const* d_in, const int* in_sizes, int n_in,
                              void* d_out, int out_size)
{
    // metadata order: codebooks [2,256,4] f32, scales [1M,1] f32, codes [2,8M] i32, rows, columns
    const float4* codebooks = (const float4*)d_in[0];
    const float*  scales    = (const float*)d_in[1];
    const int*    codes     = (const int*)d_in[2];
    float4*       out4      = (float4*)d_out;

    dequant_kernel<<<GRID, BLOCK>>>(codebooks, scales, codes, out4);
}